// round 11
// baseline (speedup 1.0000x reference)
#include <cuda_runtime.h>
#include <cfloat>
#include <cstdint>

#define BATCH 32
#define PTS   1024
#define KNN   20
#define NPTS  (BATCH*PTS)

// ---------------- device scratch (no allocations allowed) ----------------
__device__ float g_keys[NPTS*1024];   // full pairwise key matrix (134MB), reused
__device__ int   g_idx1[NPTS*KNN];    // kNN in pos space
__device__ float g_x1  [NPTS*64];     // conv1 output
__device__ float g_x1sq[NPTS];        // |x1|^2 per point
__device__ int   g_idx2[NPTS*KNN];    // kNN in feature space
__device__ float g_z   [NPTS*128];    // x1_j @ Wb
__device__ float g_s   [NPTS*128];    // x1_i @ (Wt-Wb) + b
__device__ float g_x2  [NPTS*128];    // conv2 output

// packed fp32x2 fma (Blackwell FFMA2): d = a*b + c lane-wise, exact fp32 FMA
__device__ __forceinline__ float2 ffma2(float2 a, float2 b, float2 c){
    float2 d;
    asm("fma.rn.f32x2 %0, %1, %2, %3;"
        : "=l"(*(unsigned long long*)&d)
        : "l"(*(unsigned long long*)&a),
          "l"(*(unsigned long long*)&b),
          "l"(*(unsigned long long*)&c));
    return d;
}

// ordered-uint encoding for float atomicMax (handles negatives)
__device__ __forceinline__ unsigned f2key(float f){
    unsigned u = __float_as_uint(f);
    return (u & 0x80000000u) ? ~u : (u | 0x80000000u);
}
__device__ __forceinline__ float key2f(unsigned u){
    unsigned b = (u & 0x80000000u) ? (u & 0x7FFFFFFFu) : ~u;
    return __uint_as_float(b);
}

// ---------------- init + decode output ----------------
__global__ void init_out_kernel(unsigned* out){
    int t = blockIdx.x*blockDim.x + threadIdx.x;
    if (t < BATCH*128) out[t] = 0u;   // encodes -inf
}
__global__ void decode_out_kernel(unsigned* out){
    int t = blockIdx.x*blockDim.x + threadIdx.x;
    if (t < BATCH*128) out[t] = __float_as_uint(key2f(out[t]));
}

// ---------------- kernel A: pairwise 3D distances -> g_keys ----------------
__global__ __launch_bounds__(256) void dist_pos_kernel(const float* __restrict__ pos){
    __shared__ float si[3][128], sj[3][128];
    int cloud = blockIdx.z, base = cloud*PTS;
    int i0 = blockIdx.y*128, j0 = blockIdx.x*128;
    int tid = threadIdx.x;
    if (tid < 128){
        const float* p = &pos[(base+i0+tid)*3];
        si[0][tid]=p[0]; si[1][tid]=p[1]; si[2][tid]=p[2];
    } else {
        int t = tid-128;
        const float* p = &pos[(base+j0+t)*3];
        sj[0][t]=p[0]; sj[1][t]=p[1]; sj[2][t]=p[2];
    }
    __syncthreads();
    int tx = tid & 15, ty = tid >> 4;
    float bx[8], by[8], bz[8];
    #pragma unroll
    for (int c=0;c<8;c++){ bx[c]=sj[0][tx*8+c]; by[c]=sj[1][tx*8+c]; bz[c]=sj[2][tx*8+c]; }
    #pragma unroll
    for (int r=0;r<8;r++){
        int row = ty*8+r;
        float ax = si[0][row], ay = si[1][row], az = si[2][row];
        float d[8];
        #pragma unroll
        for (int c=0;c<8;c++){
            float dx = ax-bx[c], dy = ay-by[c], dz = az-bz[c];
            d[c] = dx*dx + dy*dy + dz*dz;
        }
        float* dst = &g_keys[(base+i0+row)*1024 + j0 + tx*8];
        *(float4*)dst     = make_float4(d[0],d[1],d[2],d[3]);
        *(float4*)(dst+4) = make_float4(d[4],d[5],d[6],d[7]);
    }
}

// ---------------- kernel B: Gram-based feature keys -> g_keys (f32x2) ----------
// key[i][j] = |xj|^2 - 2 <xi,xj>; acc float2 = even/odd-k partial sums.
__global__ __launch_bounds__(512) void feat_keys_kernel(){
    extern __shared__ float sm[];
    float* sXi = sm;          // 128*64, XOR-swizzled float4 groups
    float* sXj = sm + 8192;
    float* sSq = sm + 16384;  // 128
    int cloud = blockIdx.z, base = cloud*PTS;
    int i0 = blockIdx.y*128, j0 = blockIdx.x*128;
    int tid = threadIdx.x;
    for (int t = tid; t < 2048; t += 512){
        int row = t >> 4, g = t & 15;
        float4 v = *(const float4*)&g_x1[(base+i0+row)*64 + g*4];
        *(float4*)&sXi[row*64 + ((g ^ (row>>3))<<2)] = v;
    }
    for (int t = tid; t < 2048; t += 512){
        int row = t >> 4, g = t & 15;
        float4 v = *(const float4*)&g_x1[(base+j0+row)*64 + g*4];
        *(float4*)&sXj[row*64 + ((g ^ (row>>3))<<2)] = v;
    }
    if (tid < 128) sSq[tid] = g_x1sq[base+j0+tid];
    __syncthreads();

    int tx = tid & 15, ty = tid >> 4;        // ty 0..31: 4 rows; tx: 8 cols
    int aswz = ty >> 1;                      // (ty*4+r)>>3, constant over r
    float2 acc[4][8];
    #pragma unroll
    for (int r=0;r<4;r++)
        #pragma unroll
        for (int c=0;c<8;c++) acc[r][c] = make_float2(0.f,0.f);

    #pragma unroll 2
    for (int k4=0;k4<16;k4++){
        float4 b4[8];
        int ag = ((k4 ^ aswz) << 2), bg = ((k4 ^ tx) << 2);
        #pragma unroll
        for (int c=0;c<8;c++) b4[c] = *(const float4*)&sXj[(tx*8+c)*64 + bg];
        #pragma unroll
        for (int r=0;r<4;r++){
            float4 a4 = *(const float4*)&sXi[(ty*4+r)*64 + ag];
            const float2* ap = (const float2*)&a4;
            #pragma unroll
            for (int c=0;c<8;c++){
                const float2* bp = (const float2*)&b4[c];
                acc[r][c] = ffma2(ap[0], bp[0], acc[r][c]);
                acc[r][c] = ffma2(ap[1], bp[1], acc[r][c]);
            }
        }
    }

    #pragma unroll
    for (int r=0;r<4;r++){
        int row = ty*4+r;
        float4 o0, o1;
        o0.x = fmaf(-2.f, acc[r][0].x+acc[r][0].y, sSq[tx*8+0]);
        o0.y = fmaf(-2.f, acc[r][1].x+acc[r][1].y, sSq[tx*8+1]);
        o0.z = fmaf(-2.f, acc[r][2].x+acc[r][2].y, sSq[tx*8+2]);
        o0.w = fmaf(-2.f, acc[r][3].x+acc[r][3].y, sSq[tx*8+3]);
        o1.x = fmaf(-2.f, acc[r][4].x+acc[r][4].y, sSq[tx*8+4]);
        o1.y = fmaf(-2.f, acc[r][5].x+acc[r][5].y, sSq[tx*8+5]);
        o1.z = fmaf(-2.f, acc[r][6].x+acc[r][6].y, sSq[tx*8+6]);
        o1.w = fmaf(-2.f, acc[r][7].x+acc[r][7].y, sSq[tx*8+7]);
        float* dst = &g_keys[(base+i0+row)*1024 + j0 + tx*8];
        *(float4*)dst     = o0;
        *(float4*)(dst+4) = o1;
    }
}

// ---------------- kernel C: top-20 selection from g_keys rows ----------------
__global__ __launch_bounds__(256) void select_kernel(int* __restrict__ outIdx){
    __shared__ float mk[64*80];
    int tid = threadIdx.x;
    int rl = tid >> 2, s = tid & 3;
    int row = blockIdx.x*64 + rl;
    int jbase = (row >> 10) << 10;
    const float4* krow = (const float4*)&g_keys[row*1024];

    float bd[KNN]; int bj[KNN];
    #pragma unroll
    for (int k=0;k<KNN;k++){ bd[k]=FLT_MAX; bj[k]=row & 1023; }
    float worst = FLT_MAX; int wpos = 0;

    auto ins = [&](float d, int j){
        if (d < worst){
            bd[wpos]=d; bj[wpos]=j;
            worst = bd[0]; wpos = 0;
            #pragma unroll
            for (int k=1;k<KNN;k++) if (bd[k] > worst){ worst = bd[k]; wpos = k; }
        }
    };

    for (int c = s; c < 256; c += 4){
        float4 v = krow[c];
        int j0 = c*4;
        ins(v.x, j0); ins(v.y, j0+1); ins(v.z, j0+2); ins(v.w, j0+3);
    }

    int cb = rl*80, off = s*20;
    #pragma unroll
    for (int k=0;k<KNN;k++) mk[cb+off+k] = bd[k];
    __syncthreads();
    #pragma unroll
    for (int k=0;k<KNN;k++){
        float kc = bd[k]; int cpos = off + k;
        int rank = 0;
        for (int q=0;q<80;q++){
            float kq = mk[cb+q];
            rank += (kq < kc) || (kq == kc && q < cpos);
        }
        if (rank < KNN) outIdx[row*KNN+rank] = jbase + bj[k];
    }
}

// ---------------- kernel 2: EdgeConv1 — transposed H + packed f32x2 layer2 ----
// dyn smem (floats): sW1f[384] | sb1f[64] | sb2[64] | sW2[4096] | Ht[8][64*36]
#define HT_STR 36
__global__ __launch_bounds__(256) void conv1_kernel(
    const float* __restrict__ pos,
    const float* __restrict__ W1, const float* __restrict__ b1,
    const float* __restrict__ bns, const float* __restrict__ bnb,
    const float* __restrict__ W2, const float* __restrict__ b2)
{
    extern __shared__ float smc[];
    float* sW1f = smc;            // 384
    float* sb1f = smc + 384;      // 64
    float* sb2  = smc + 448;      // 64
    float* sW2  = smc + 512;      // 4096
    float* sHt  = smc + 4608;     // 8 * 64*HT_STR

    int tid = threadIdx.x;
    for (int t = tid; t < 64; t += 256){
        float sc = bns[t];
        sb1f[t] = b1[t]*sc + bnb[t];    // fold BN into layer-1 affine
        sb2[t]  = b2[t];
        #pragma unroll
        for (int d=0; d<6; d++) sW1f[d*64+t] = W1[d*64+t]*sc;
    }
    for (int t = tid; t < 4096; t += 256) sW2[t] = W2[t];
    __syncthreads();

    int warp = tid >> 5, lane = tid & 31;
    int i = blockIdx.x*8 + warp;
    float xi0 = pos[i*3+0], xi1 = pos[i*3+1], xi2 = pos[i*3+2];
    float* Ht = sHt + warp*(64*HT_STR);   // Ht[k][j], row stride HT_STR
    int c0 = lane, c1 = lane + 32;

    float w3a = sW1f[192+c0], w4a = sW1f[256+c0], w5a = sW1f[320+c0];
    float w3b = sW1f[192+c1], w4b = sW1f[256+c1], w5b = sW1f[320+c1];
    float basea = sb1f[c0] + xi0*sW1f[c0] + xi1*sW1f[64+c0] + xi2*sW1f[128+c0];
    float baseb = sb1f[c1] + xi0*sW1f[c1] + xi1*sW1f[64+c1] + xi2*sW1f[128+c1];

    // layer 1: per-edge hidden, relu; store TRANSPOSED Ht[k][j] (k = own column)
    #pragma unroll
    for (int j4=0; j4<5; j4++){
        float h0[4], h1[4];
        #pragma unroll
        for (int jj=0; jj<4; jj++){
            int j = j4*4 + jj;
            int n = g_idx1[i*KNN+j];
            float d0 = pos[n*3+0]-xi0, d1 = pos[n*3+1]-xi1, d2 = pos[n*3+2]-xi2;
            h0[jj] = fmaxf(basea + d0*w3a + d1*w4a + d2*w5a, 0.f);
            h1[jj] = fmaxf(baseb + d0*w3b + d1*w4b + d2*w5b, 0.f);
        }
        *(float4*)&Ht[c0*HT_STR + j4*4] = make_float4(h0[0],h0[1],h0[2],h0[3]);
        *(float4*)&Ht[c1*HT_STR + j4*4] = make_float4(h1[0],h1[1],h1[2],h1[3]);
    }
    __syncwarp();

    // layer 2: packed f32x2 over j-pairs; weight scalar dup reused across 10 pairs
    float2 acc0[10], acc1[10];
    #pragma unroll
    for (int p=0;p<10;p++){ acc0[p]=make_float2(0.f,0.f); acc1[p]=make_float2(0.f,0.f); }
    #pragma unroll 4
    for (int k=0;k<64;k++){
        float w0 = sW2[k*64+c0];
        float w1 = sW2[k*64+c1];
        float2 w0d = make_float2(w0,w0);
        float2 w1d = make_float2(w1,w1);
        const float4* hr = (const float4*)&Ht[k*HT_STR];
        #pragma unroll
        for (int g=0; g<5; g++){
            float4 h = hr[g];                      // broadcast LDS.128
            float2 p0 = make_float2(h.x,h.y);
            float2 p1 = make_float2(h.z,h.w);
            acc0[g*2]   = ffma2(p0, w0d, acc0[g*2]);
            acc0[g*2+1] = ffma2(p1, w0d, acc0[g*2+1]);
            acc1[g*2]   = ffma2(p0, w1d, acc1[g*2]);
            acc1[g*2+1] = ffma2(p1, w1d, acc1[g*2+1]);
        }
    }
    float m0 = -FLT_MAX, m1 = -FLT_MAX;
    #pragma unroll
    for (int p=0;p<10;p++){
        m0 = fmaxf(m0, fmaxf(acc0[p].x, acc0[p].y));
        m1 = fmaxf(m1, fmaxf(acc1[p].x, acc1[p].y));
    }
    m0 += sb2[c0];
    m1 += sb2[c1];
    g_x1[i*64+c0] = m0;
    g_x1[i*64+c1] = m1;
    float sq = m0*m0 + m1*m1;
    #pragma unroll
    for (int o=16;o;o>>=1) sq += __shfl_xor_sync(0xffffffffu, sq, o);
    if (lane == 0) g_x1sq[i] = sq;
}

// ---------------- kernel 4: z = x1@Wb, s = x1@(Wt-Wb)+b  (col-pair f32x2) ------
__global__ __launch_bounds__(256) void zs_kernel(const float* __restrict__ c2W,
                                                 const float* __restrict__ c2b){
    extern __shared__ float sm4[];
    float* sW = sm4;            // 128*128
    float* sx = sm4 + 16384;    // 8 warps * 2 pts * 64
    int tid = threadIdx.x, warp = tid>>5, lane = tid&31;
    for (int t=tid; t<16384; t+=256) sW[t] = c2W[t];
    __syncthreads();
    int c0 = 2*lane, c1 = 64 + 2*lane;
    float2 cb0 = make_float2(c2b[c0], c2b[c0+1]);
    float2 cb1 = make_float2(c2b[c1], c2b[c1+1]);

    for (int g = blockIdx.x; g < NPTS/16; g += gridDim.x){
        int i0 = g*16 + warp*2;
        float* xw = sx + warp*128;
        xw[lane]      = g_x1[i0*64 + lane];
        xw[lane+32]   = g_x1[i0*64 + 32 + lane];
        xw[64+lane]   = g_x1[(i0+1)*64 + lane];
        xw[96+lane]   = g_x1[(i0+1)*64 + 32 + lane];
        __syncwarp();
        float2 at00=make_float2(0,0), at01=at00, az00=at00, az01=at00;
        float2 at10=at00, at11=at00, az10=at00, az11=at00;
        #pragma unroll 4
        for (int k=0;k<64;k++){
            float x0 = xw[k], x1v = xw[64+k];
            float2 x0d = make_float2(x0,x0), x1d = make_float2(x1v,x1v);
            float2 wt0 = *(const float2*)&sW[k*128 + c0];
            float2 wt1 = *(const float2*)&sW[k*128 + c1];
            float2 wb0 = *(const float2*)&sW[(k+64)*128 + c0];
            float2 wb1 = *(const float2*)&sW[(k+64)*128 + c1];
            at00 = ffma2(x0d, wt0, at00);  az00 = ffma2(x0d, wb0, az00);
            at01 = ffma2(x0d, wt1, at01);  az01 = ffma2(x0d, wb1, az01);
            at10 = ffma2(x1d, wt0, at10);  az10 = ffma2(x1d, wb0, az10);
            at11 = ffma2(x1d, wt1, at11);  az11 = ffma2(x1d, wb1, az11);
        }
        *(float2*)&g_z[i0*128 + c0]     = az00;
        *(float2*)&g_z[i0*128 + c1]     = az01;
        *(float2*)&g_z[(i0+1)*128 + c0] = az10;
        *(float2*)&g_z[(i0+1)*128 + c1] = az11;
        *(float2*)&g_s[i0*128 + c0]     = make_float2(at00.x-az00.x+cb0.x, at00.y-az00.y+cb0.y);
        *(float2*)&g_s[i0*128 + c1]     = make_float2(at01.x-az01.x+cb1.x, at01.y-az01.y+cb1.y);
        *(float2*)&g_s[(i0+1)*128 + c0] = make_float2(at10.x-az10.x+cb0.x, at10.y-az10.y+cb0.y);
        *(float2*)&g_s[(i0+1)*128 + c1] = make_float2(at11.x-az11.x+cb1.x, at11.y-az11.y+cb1.y);
        __syncwarp();
    }
}

// ---------------- kernel 5: gather-max -> x2 ----------------
__global__ __launch_bounds__(256) void gather_kernel(){
    int gw   = (blockIdx.x*blockDim.x + threadIdx.x) >> 5;
    int lane = threadIdx.x & 31;
    if (gw >= NPTS) return;
    const int* idx = &g_idx2[gw*KNN];
    float4 m = make_float4(-FLT_MAX,-FLT_MAX,-FLT_MAX,-FLT_MAX);
    #pragma unroll
    for (int j=0;j<KNN;j++){
        int n = idx[j];
        float4 v = *(const float4*)&g_z[n*128 + lane*4];
        m.x = fmaxf(m.x, v.x); m.y = fmaxf(m.y, v.y);
        m.z = fmaxf(m.z, v.z); m.w = fmaxf(m.w, v.w);
    }
    float4 sv = *(const float4*)&g_s[gw*128 + lane*4];
    float4 r  = make_float4(sv.x+m.x, sv.y+m.y, sv.z+m.z, sv.w+m.w);
    *(float4*)&g_x2[gw*128 + lane*4] = r;
}

// ---------------- kernel 6: lin([x1,x2]) + global max pool (col-pair f32x2) ----
__global__ __launch_bounds__(512) void linpool_kernel(const float* __restrict__ lW,
                                                      const float* __restrict__ lb,
                                                      unsigned* __restrict__ out){
    extern __shared__ float sm6[];
    float* sW = sm6;              // 192*128
    float* sx = sm6 + 192*128;    // 16 warps * 4 pts * 192
    int tid = threadIdx.x, warp = tid>>5, lane = tid&31;
    for (int t=tid; t<192*128; t+=512) sW[t] = lW[t];
    __syncthreads();
    int c0 = 2*lane, c1 = 64 + 2*lane;
    float2 lb0 = make_float2(lb[c0], lb[c0+1]);
    float2 lb1 = make_float2(lb[c1], lb[c1+1]);

    for (int ch = blockIdx.x*16 + warp; ch < NPTS/4; ch += gridDim.x*16){
        int p0 = ch*4;
        float* xw = sx + warp*4*192;
        #pragma unroll
        for (int pt=0; pt<4; pt++){
            int p = p0 + pt;
            #pragma unroll
            for (int t6=0; t6<6; t6++){
                int t = lane + t6*32;
                xw[pt*192 + t] = (t < 64) ? g_x1[p*64 + t] : g_x2[p*128 + (t-64)];
            }
        }
        __syncwarp();
        float2 acc[4][2];
        #pragma unroll
        for (int pt=0;pt<4;pt++){ acc[pt][0]=make_float2(0,0); acc[pt][1]=make_float2(0,0); }
        #pragma unroll 4
        for (int k=0;k<192;k++){
            float2 w0 = *(const float2*)&sW[k*128 + c0];
            float2 w1 = *(const float2*)&sW[k*128 + c1];
            #pragma unroll
            for (int pt=0;pt<4;pt++){
                float xv = xw[pt*192+k];
                float2 xd = make_float2(xv,xv);
                acc[pt][0] = ffma2(xd, w0, acc[pt][0]);
                acc[pt][1] = ffma2(xd, w1, acc[pt][1]);
            }
        }
        int cloud = p0 >> 10;
        float2 m0 = acc[0][0], m1 = acc[0][1];
        #pragma unroll
        for (int pt=1;pt<4;pt++){
            m0.x = fmaxf(m0.x, acc[pt][0].x); m0.y = fmaxf(m0.y, acc[pt][0].y);
            m1.x = fmaxf(m1.x, acc[pt][1].x); m1.y = fmaxf(m1.y, acc[pt][1].y);
        }
        m0.x += lb0.x; m0.y += lb0.y; m1.x += lb1.x; m1.y += lb1.y;
        atomicMax(&out[cloud*128 + c0],     f2key(m0.x));
        atomicMax(&out[cloud*128 + c0 + 1], f2key(m0.y));
        atomicMax(&out[cloud*128 + c1],     f2key(m1.x));
        atomicMax(&out[cloud*128 + c1 + 1], f2key(m1.y));
        __syncwarp();
    }
}

// ---------------- launch ----------------
extern "C" void kernel_launch(void* const* d_in, const int* in_sizes, int n_in,
                              void* d_out, int out_size)
{
    const float* pos  = (const float*)d_in[0];
    const float* c1W1 = (const float*)d_in[2];
    const float* c1b1 = (const float*)d_in[3];
    const float* bns  = (const float*)d_in[4];
    const float* bnb  = (const float*)d_in[5];
    const float* c1W2 = (const float*)d_in[6];
    const float* c1b2 = (const float*)d_in[7];
    const float* c2W  = (const float*)d_in[8];
    const float* c2b  = (const float*)d_in[9];
    const float* lW   = (const float*)d_in[10];
    const float* lb   = (const float*)d_in[11];
    unsigned* out = (unsigned*)d_out;

    int* d_idx1; cudaGetSymbolAddress((void**)&d_idx1, g_idx1);
    int* d_idx2; cudaGetSymbolAddress((void**)&d_idx2, g_idx2);

    const int C1_SMEM = (4608 + 8*64*HT_STR) * 4;          // 92,160 B
    const int FK_SMEM = (8192*2 + 128) * 4;                // 66,048 B
    const int ZS_SMEM = (16384 + 8*128) * 4;               // 69,632 B
    const int LP_SMEM = (192*128 + 16*4*192) * 4;          // 147,456 B
    cudaFuncSetAttribute(conv1_kernel,     cudaFuncAttributeMaxDynamicSharedMemorySize, C1_SMEM);
    cudaFuncSetAttribute(feat_keys_kernel, cudaFuncAttributeMaxDynamicSharedMemorySize, FK_SMEM);
    cudaFuncSetAttribute(zs_kernel,        cudaFuncAttributeMaxDynamicSharedMemorySize, ZS_SMEM);
    cudaFuncSetAttribute(linpool_kernel,   cudaFuncAttributeMaxDynamicSharedMemorySize, LP_SMEM);

    init_out_kernel<<<16, 256>>>(out);
    dist_pos_kernel<<<dim3(8,8,BATCH), 256>>>(pos);
    select_kernel<<<NPTS/64, 256>>>(d_idx1);
    conv1_kernel<<<NPTS/8, 256, C1_SMEM>>>(pos, c1W1, c1b1, bns, bnb, c1W2, c1b2);
    feat_keys_kernel<<<dim3(8,8,BATCH), 512, FK_SMEM>>>();
    select_kernel<<<NPTS/64, 256>>>(d_idx2);
    zs_kernel<<<444, 256, ZS_SMEM>>>(c2W, c2b);
    gather_kernel<<<NPTS/8, 256>>>();
    linpool_kernel<<<148, 512, LP_SMEM>>>(lW, lb, out);
    decode_out_kernel<<<16, 256>>>(out);
}